// round 10
// baseline (speedup 1.0000x reference)
#include <cuda_runtime.h>
#include <cuda_fp16.h>
#include <math.h>
#include <stdint.h>

// ===========================================================================
// VoxelConvolution via mma.sync m16n8k16 FP16 (fp32 accum) implicit GEMM.
//   pad_k   : x -> xp transposed [dz][hz][wz][perm(ci)] fp16, smem-transposed
//   build_k : weights -> g_frag[tap][kb16][mt][lane][4regs][2] fp16 fragments
//   conv_k  : CTA tile M=128 x N=192 (8h x 24w); 12 warps = 4 m-quarters x
//             3 n-blocks (balances A-L1 vs B-smem operand traffic);
//             double-buffered B slab per (a,b) plane; kb-level A/B prefetch.
// ===========================================================================

#define PADW 52
__device__ __half xp[PADW * PADW * PADW * 128];   // 36 MB transposed fp16 input
__device__ __half g_frag[125 * 16384];            // 4 MB A fragments

// within-16 k permutation: storage pos for k is 4*((k&7)>>1)+2*((k>>3)&1)+(k&1)
// -> positions 4q..4q+3 hold k = {2q, 2q+1, 2q+8, 2q+9}  (one LDS.64 per B frag)
__device__ __forceinline__ int pos16(int ci) {           // k -> storage pos
    return (ci & ~15) | (4 * ((ci & 7) >> 1) + 2 * ((ci >> 3) & 1) + (ci & 1));
}
// A fragment half-index within a tap (16384 halfs):
// [kb 8][mt 8][lane 32][reg 4][half 2]
__device__ __forceinline__ int frag_off16(int o, int ci) {
    int kb   = ci >> 4;
    int lane = (o & 7) * 4 + ((ci & 7) >> 1);
    int reg  = ((ci >> 3) & 1) * 2 + ((o >> 3) & 1);
    int mt   = o >> 4;
    return (((kb * 8 + mt) * 32 + lane) * 4 + reg) * 2 + (ci & 1);
}

__device__ __forceinline__ void mma16(float* c, const uint4& a, const uint32_t* b) {
    asm volatile(
        "mma.sync.aligned.m16n8k16.row.col.f32.f16.f16.f32 "
        "{%0,%1,%2,%3}, {%4,%5,%6,%7}, {%8,%9}, {%0,%1,%2,%3};"
        : "+f"(c[0]), "+f"(c[1]), "+f"(c[2]), "+f"(c[3])
        : "r"(a.x), "r"(a.y), "r"(a.z), "r"(a.w), "r"(b[0]), "r"(b[1]));
}
__device__ __forceinline__ uint32_t smem_u32(const void* p) {
    uint32_t a;
    asm("{ .reg .u64 t; cvta.to.shared.u64 t, %1; cvt.u32.u64 %0, t; }" : "=r"(a) : "l"(p));
    return a;
}

// ---------------------------------------------------------------------------
// pad_k: one block per (dz, hz) plane; smem transpose, coalesced both sides.
// ---------------------------------------------------------------------------
#define TR_STRIDE 136
__global__ void __launch_bounds__(256) pad_k(const float* __restrict__ x) {
    const int dz = blockIdx.x, hz = blockIdx.y;
    const int tid = threadIdx.x;
    __half* dst = xp + ((size_t)dz * PADW + hz) * PADW * 128;

    if (dz < 2 || dz >= 50 || hz < 2 || hz >= 50) {
        uint4 z = make_uint4(0, 0, 0, 0);
        for (int i = tid; i < 832; i += 256) ((uint4*)dst)[i] = z;
        return;
    }

    __shared__ __half sm[48 * TR_STRIDE];
    const float* src = x + (size_t)(dz - 2) * 48 * 48 + (size_t)(hz - 2) * 48;
    for (int idx = tid; idx < 128 * 48; idx += 256) {
        int ci = idx / 48, wz = idx % 48;
        float v = src[(size_t)ci * 48 * 48 * 48 + wz];
        sm[wz * TR_STRIDE + pos16(ci)] = __float2half_rn(v);
    }
    __syncthreads();
    for (int e = tid; e < 48 * 16; e += 256) {
        int wz = e >> 4, ch = e & 15;
        *(uint4*)(dst + (wz + 2) * 128 + ch * 8) =
            *(const uint4*)(sm + wz * TR_STRIDE + ch * 8);
    }
    uint4 z = make_uint4(0, 0, 0, 0);
    for (int e = tid; e < 64; e += 256) {
        int r = e >> 4, ch = e & 15;
        int wz = (r < 2) ? r : 48 + r;
        *(uint4*)(dst + wz * 128 + ch * 8) = z;
    }
}

// ---------------------------------------------------------------------------
__global__ void build_k(const float* __restrict__ weight,   // [8][4096]
                        const float* __restrict__ scws,     // [32][32]
                        const float* __restrict__ scwv) {   // [32][32]
    int t = blockIdx.x;            // 0..124
    int a = t / 25, b = (t / 5) % 5, c = t % 5;

    __shared__ float emb_s[8];
    __shared__ float shv_s[3];
    if (threadIdx.x == 0) {
        double dx = a - 2, dy = b - 2, dz = c - 2;
        double d = sqrt(dx * dx + dy * dy + dz * dz);
        double step = 2.5 / 9.0;
        const double SMOOTH_C = 1.14136 * exp(2.0);
        for (int rb = 0; rb < 8; ++rb) {
            double val = (rb + 1) * step;
            double diff = (d - val) / step;
            double f = 0.0;
            if (fabs(diff) < 1.0) {
                double dc = diff;
                if (dc < -1.0 + 1e-6) dc = -1.0 + 1e-6;
                if (dc >  1.0 - 1e-6) dc =  1.0 - 1e-6;
                f = SMOOTH_C * exp(-1.0 / (1.0 + dc)) * exp(-1.0 / (1.0 - dc));
            }
            emb_s[rb] = (float)f;
        }
        double nn = d > 1e-12 ? d : 1e-12;
        const double SQ3 = 1.7320508075688772;
        shv_s[0] = (float)(SQ3 * dx / nn);
        shv_s[1] = (float)(SQ3 * dy / nn);
        shv_s[2] = (float)(SQ3 * dz / nn);
    }
    __syncthreads();

    const float PW0  = 0.125f;
    const float PW1  = 0.21650635094610965f;
    const float SQ3f = 1.7320508075688772f;
    const float INV  = 0.17677669529663687f;
    const float INV_NVOX = 1.0f / 81.0f;

    __half* A = g_frag + (size_t)t * 16384;

    for (int p = threadIdx.x; p < 1024; p += blockDim.x) {
        int u  = p >> 5;   // input mul
        int wm = p & 31;   // output mul
        float W[4];
#pragma unroll
        for (int cc = 0; cc < 4; ++cc) {
            float s = 0.f;
#pragma unroll
            for (int rb = 0; rb < 8; ++rb)
                s += emb_s[rb] * weight[rb * 4096 + cc * 1024 + u * 32 + wm];
            W[cc] = s * INV_NVOX;
        }
        float ksv = (PW0 / SQ3f) * W[3];
        float kvs = (PW1 / SQ3f) * W[1];
        float kvv = (PW1 / SQ3f) * W[2];

        {   // scalar->scalar (o=wm, ci=u) + center self-connection
            float v = PW0 * W[0];
            if (t == 62) v += INV * scws[u * 32 + wm] * INV_NVOX;
            A[frag_off16(wm, u)] = __float2half_rn(v);
        }
#pragma unroll
        for (int i = 0; i < 3; ++i)       // vector-in -> scalar-out
            A[frag_off16(wm, 32 + u * 3 + i)] = __float2half_rn(ksv * shv_s[i]);
#pragma unroll
        for (int k = 0; k < 3; ++k)       // scalar-in -> vector-out
            A[frag_off16(32 + wm * 3 + k, u)] = __float2half_rn(kvs * shv_s[k]);
#pragma unroll
        for (int i = 0; i < 3; ++i)       // vector-in -> vector-out (diag)
#pragma unroll
            for (int k = 0; k < 3; ++k) {
                float v = (i == k) ? kvv : 0.f;
                if (t == 62 && i == k) v += INV * scwv[u * 32 + wm] * INV_NVOX;
                A[frag_off16(32 + wm * 3 + k, 32 + u * 3 + i)] = __float2half_rn(v);
            }
    }
}

// ---------------------------------------------------------------------------
// conv_k: 384 threads, 12 warps = 4 m-quarters(32) x 3 n-blocks(64).
// SMEM: 2 x B slab [224 rows][144 halfs]  (2 x 64,512 B = 129,024 B).
// ---------------------------------------------------------------------------
#define BS_H      144                    // halfs per smem row (288 B)
#define BS_ROWS   224
#define BUF_HALFS (BS_ROWS * BS_H)
#define BUF_BYTES (BUF_HALFS * 2)

// 21 valid (a,b) planes; c-range: s2<=2 -> [0,4], else [1,3]
__device__ const signed char PA[21] = {0,0,0, 1,1,1,1,1, 2,2,2,2,2, 3,3,3,3,3, 4,4,4};
__device__ const signed char PB[21] = {1,2,3, 0,1,2,3,4, 0,1,2,3,4, 0,1,2,3,4, 1,2,3};

__device__ __forceinline__ void stage_plane(uint32_t base, int dz, int hz,
                                            int w0, int tid) {
    for (int e = tid; e < BS_ROWS * 16; e += 384) {
        int row = e >> 4, ch = e & 15;
        int rr = row / 28, wl = row % 28;
        const __half* src = xp + ((((size_t)dz * PADW + hz + rr) * PADW) + w0 + wl) * 128
                          + ch * 8;
        uint32_t dst = base + row * (BS_H * 2) + ch * 16;
        asm volatile("cp.async.cg.shared.global [%0], [%1], 16;"
                     :: "r"(dst), "l"(src) : "memory");
    }
}

__global__ void __launch_bounds__(384, 1) conv_k(float* __restrict__ out) {
    extern __shared__ __align__(16) __half smh[];
    const uint32_t smbase = smem_u32(smh);

    const int tid  = threadIdx.x;
    const int lane = tid & 31;
    const int g    = lane >> 2;
    const int t4   = lane & 3;
    const int warp = tid >> 5;
    const int mq   = warp & 3;          // m quarter (32 rows), 0..3
    const int nb   = warp >> 2;         // n block (64), 0..2
    const int w0   = blockIdx.x * 24;
    const int h0   = blockIdx.y * 8;
    const int d    = blockIdx.z;

    float acc[2][8][4];
#pragma unroll
    for (int i = 0; i < 2; ++i)
#pragma unroll
        for (int j = 0; j < 8; ++j)
#pragma unroll
            for (int q = 0; q < 4; ++q) acc[i][j][q] = 0.f;

    int spatj[8];
#pragma unroll
    for (int j = 0; j < 8; ++j) {
        int nl = nb * 64 + j * 8 + g;   // B frag col = groupID
        spatj[j] = (nl / 24) * 28 + (nl % 24);
    }

    // prologue: stage plane 0 into buf 0
    stage_plane(smbase, d + PA[0], h0 + PB[0], w0, tid);
    asm volatile("cp.async.commit_group;" ::: "memory");

    for (int p = 0; p < 21; ++p) {
        __syncthreads();                     // prev compute on buf[(p+1)&1] done
        if (p + 1 < 21) {
            stage_plane(smbase + ((p + 1) & 1) * BUF_BYTES,
                        d + PA[p + 1], h0 + PB[p + 1], w0, tid);
            asm volatile("cp.async.commit_group;" ::: "memory");
            asm volatile("cp.async.wait_group 1;" ::: "memory");
        } else {
            asm volatile("cp.async.wait_group 0;" ::: "memory");
        }
        __syncthreads();                     // plane p visible to all

        const int a  = PA[p], b = PB[p];
        const int s2 = (a - 2) * (a - 2) + (b - 2) * (b - 2);
        const int clo = (s2 >= 4) ? 1 : 0;
        const int chi = (s2 >= 4) ? 3 : 4;
        const __half* Bbuf = smh + (p & 1) * BUF_HALFS;

        for (int c = clo; c <= chi; ++c) {
            const int tap = (a * 5 + b) * 5 + c;
            const uint4* At = (const uint4*)g_frag + (size_t)tap * 2048
                            + mq * 64 + lane;           // mt = mq*2 + i
            const __half* Bp = Bbuf + c * BS_H + 4 * t4;

            uint4 af[2][2];
            uint32_t bf[2][8][2];
            // preload kb = 0
#pragma unroll
            for (int i = 0; i < 2; ++i)
                af[0][i] = __ldg(At + i * 32);
#pragma unroll
            for (int j = 0; j < 8; ++j) {
                uint2 v = *(const uint2*)(Bp + spatj[j] * BS_H);
                bf[0][j][0] = v.x;
                bf[0][j][1] = v.y;
            }
#pragma unroll
            for (int kb = 0; kb < 8; ++kb) {
                const int cur = kb & 1, nxt = cur ^ 1;
                if (kb < 7) {
                    const uint4* Ak = At + (kb + 1) * 256;
#pragma unroll
                    for (int i = 0; i < 2; ++i)
                        af[nxt][i] = __ldg(Ak + i * 32);
#pragma unroll
                    for (int j = 0; j < 8; ++j) {
                        uint2 v = *(const uint2*)(Bp + spatj[j] * BS_H
                                                     + (kb + 1) * 16);
                        bf[nxt][j][0] = v.x;
                        bf[nxt][j][1] = v.y;
                    }
                }
#pragma unroll
                for (int i = 0; i < 2; ++i)
#pragma unroll
                    for (int j = 0; j < 8; ++j)
                        mma16(acc[i][j], af[cur][i], bf[cur][j]);
            }
        }
    }

    // epilogue: fragment -> float2 global stores
#pragma unroll
    for (int i = 0; i < 2; ++i) {
        const int o = mq * 32 + i * 16 + g;
#pragma unroll
        for (int j = 0; j < 8; ++j) {
            const int nl = nb * 64 + j * 8 + 2 * t4;
            const int hh = h0 + nl / 24;
            const int ww = w0 + nl % 24;
            float2 v0 = make_float2(acc[i][j][0], acc[i][j][1]);
            float2 v1 = make_float2(acc[i][j][2], acc[i][j][3]);
            *(float2*)(out + (((size_t)o * 48 + d) * 48 + hh) * 48 + ww) = v0;
            *(float2*)(out + (((size_t)(o + 8) * 48 + d) * 48 + hh) * 48 + ww) = v1;
        }
    }
}

// ---------------------------------------------------------------------------
extern "C" void kernel_launch(void* const* d_in, const int* in_sizes, int n_in,
                              void* d_out, int out_size) {
    const float* x    = (const float*)d_in[0];
    const float* wt   = (const float*)d_in[1];
    const float* scws = (const float*)d_in[2];
    const float* scwv = (const float*)d_in[3];
    float* out = (float*)d_out;

    dim3 pgrid(PADW, PADW);
    pad_k<<<pgrid, 256>>>(x);
    build_k<<<125, 256>>>(wt, scws, scwv);

    const int smem_bytes = 2 * BUF_BYTES;   // 129,024 B
    cudaFuncSetAttribute(conv_k, cudaFuncAttributeMaxDynamicSharedMemorySize,
                         smem_bytes);
    dim3 grid(2, 6, 48);   // w-tiles x h-tiles x d
    conv_k<<<grid, 384, smem_bytes>>>(out);
}